// round 12
// baseline (speedup 1.0000x reference)
#include <cuda_runtime.h>
#include <math.h>

// ---------------- problem constants ----------------
#define BB   64
#define SS   250
#define CLL  16
#define CVV  100
#define CHH  50
#define FDD  5
#define WDD  300
#define CDD  300
#define HH   100
#define G4   400      // 4*H
#define INN  355      // WD + CH + FD
#define KP   360      // padded K for GEMM
#define N2   800      // both directions' gates
#define N2P  896      // padded N for GEMM loads
#define NS   (BB*SS)  // 16000
#define TT   22
#define START_TAG 20
#define STOP_TAG  21

typedef unsigned long long ull;

// ---------------- resolved input pointers ----------------
__device__ const int   *P_word, *P_feat, *P_len, *P_char, *P_rec;
__device__ const float *P_cemb, *P_wemb, *P_femb, *P_cw, *P_cb;
__device__ const float *P_wihf, *P_whhf, *P_bf, *P_wihb, *P_whhb, *P_bb;
__device__ const float *P_pw, *P_pb, *P_tr;

// ---------------- scratch ----------------
__device__ float g_proj[CVV*3*CHH];
__device__ float g_charmax[NS*CHH];
__device__ float g_W[KP*N2P];
__device__ float g_pre[NS*N2];
__device__ float g_lstm[NS*(2*HH)];
__device__ float g_feats[NS*TT];

// MUFU-based activations (same formulas as R11, rel_err 0.0)
__device__ __forceinline__ float sigf(float x) {
    return __fdividef(1.0f, 1.0f + __expf(-x));
}

// ---------------- packed fp32x2 helpers ----------------
__device__ __forceinline__ ull ffma2(ull a, ull b, ull c) {
    ull d;
    asm("fma.rn.f32x2 %0, %1, %2, %3;" : "=l"(d) : "l"(a), "l"(b), "l"(c));
    return d;
}
__device__ __forceinline__ ull faddx2(ull a, ull b) {
    ull d;
    asm("add.rn.f32x2 %0, %1, %2;" : "=l"(d) : "l"(a), "l"(b));
    return d;
}
__device__ __forceinline__ ull fdup(float a) {
    ull r;
    asm("mov.b64 %0, {%1, %1};" : "=l"(r) : "f"(a));
    return r;
}
__device__ __forceinline__ ull fpk(float a, float b) {
    ull r;
    asm("mov.b64 %0, {%1, %2};" : "=l"(r) : "f"(a), "f"(b));
    return r;
}
__device__ __forceinline__ float2 fupk(ull v) {
    float2 f;
    asm("mov.b64 {%0, %1}, %2;" : "=f"(f.x), "=f"(f.y) : "l"(v));
    return f;
}

// ---------------- host-resolved fixed pointers ----------------
struct FixedPtrs {
    const float *wemb, *cemb, *cw, *pw, *pb, *tr;
    const float *wihf, *wihb, *whhf, *whhb, *bf, *bb;
    const int   *chr, *len;
    const int   *c16[5]; int n16;
    const float *c50[2]; int n50;
};

// ---------------- K0: fused resolve + buildW + charproj ----------------
__global__ __launch_bounds__(512, 2)
void k_init(FixedPtrs fp) {
    int bid = blockIdx.x;
    if (bid == 0) {
        int w = threadIdx.x >> 5, lane = threadIdx.x & 31;
        if (w < fp.n16 && w < 5) {
            const int* v = fp.c16[w];
            bool isrec = true, ble1 = true;
            int mn = 0x7fffffff, mx = -0x7fffffff;
            #pragma unroll
            for (int k = lane; k < 256; k += 32) {
                int x = v[k];
                if (x != k) isrec = false;
                unsigned u = (unsigned)x;
                if (((u)&0xFFu) > 1u || ((u>>8)&0xFFu) > 1u ||
                    ((u>>16)&0xFFu) > 1u || ((u>>24)&0xFFu) > 1u) ble1 = false;
                mn = min(mn, x); mx = max(mx, x);
            }
            isrec = __all_sync(0xffffffffu, isrec);
            ble1  = __all_sync(0xffffffffu, ble1);
            #pragma unroll
            for (int off = 16; off; off >>= 1) {
                mn = min(mn, __shfl_xor_sync(0xffffffffu, mn, off));
                mx = max(mx, __shfl_xor_sync(0xffffffffu, mx, off));
            }
            if (lane == 0) {
                if (isrec)                    P_rec  = v;
                else if (ble1)                { /* mask: unused */ }
                else if (mn >= 0 && mx <= 9)  P_feat = v;
                else if (mn >= 1 && mx <= 16) { /* charlen: unused */ }
                else                          P_word = v;
            }
        } else if (w == 5) {
            for (int j = 0; j < fp.n50; j++) {
                const float* f = fp.c50[j];
                bool nz = false;
                for (int k = lane; k < 50; k += 32) nz |= (f[k] != 0.0f);
                bool anynz = __any_sync(0xffffffffu, nz);
                if (lane == 0) { if (anynz) P_femb = f; else P_cb = f; }
            }
        } else if (w == 6 && lane == 0) {
            P_wemb = fp.wemb; P_cemb = fp.cemb; P_cw = fp.cw;
            P_pw = fp.pw; P_pb = fp.pb; P_tr = fp.tr;
            P_wihf = fp.wihf; P_wihb = fp.wihb;
            P_whhf = fp.whhf; P_whhb = fp.whhb;
            P_bf = fp.bf; P_bb = fp.bb;
            P_char = fp.chr; P_len = fp.len;
        }
    } else if (bid <= 630) {
        int idx = (bid - 1)*512 + threadIdx.x;   // 630*512 == KP*N2P exactly
        int k = idx / N2P, g2 = idx % N2P;
        float v = 0.f;
        if (k < INN && g2 < N2) {
            v = (g2 < G4) ? fp.wihf[g2*INN + k] : fp.wihb[(g2-G4)*INN + k];
        }
        g_W[idx] = v;
    } else {
        const float* char_emb = fp.cemb;
        const float* conv_w   = fp.cw;
        __shared__ float sce[CDD];
        int c = bid - 631;
        for (int d = threadIdx.x; d < CDD; d += blockDim.x)
            sce[d] = char_emb[c*CDD + d];
        __syncthreads();
        int tid = threadIdx.x;
        if (tid < 3*CHH) {
            int k = tid / CHH, o = tid % CHH;
            float acc = 0.f;
            #pragma unroll 4
            for (int d = 0; d < CDD; d++)
                acc += __ldg(conv_w + (o*CDD + d)*3 + k) * sce[d];
            g_proj[(c*3 + k)*CHH + o] = acc;
        }
    }
}

// ---------------- K1: char conv + max-pool ----------------
__global__ void k_charmax() {
    const int*   batch_char = P_char;
    const float* conv_b     = P_cb;
    __shared__ int chs[4][CLL];
    int t = threadIdx.x & 63;
    int ns = threadIdx.x >> 6;
    int n = blockIdx.x*4 + ns;
    if (t < CLL) chs[ns][t] = batch_char[n*CLL + t];
    __syncthreads();
    if (t < CHH) {
        float bo = conv_b[t];
        float best = -1e30f;
        #pragma unroll
        for (int p = 0; p < CLL; p++) {
            float v = bo;
            #pragma unroll
            for (int k = 0; k < 3; k++) {
                int q = p + k - 1;
                if (q >= 0 && q < CLL)
                    v += __ldg(&g_proj[(chs[ns][q]*3 + k)*CHH + t]);
            }
            best = fmaxf(best, v);
        }
        g_charmax[n*CHH + t] = best;
    }
}

// ---------------- K2: SGEMM, fused A-gather, double-buffered ----------------
#define BM 128
#define BN 128
#define BKK 8
#define NT (KP/BKK)   // 45
__global__ __launch_bounds__(256, 2)
void k_gemm() {
    const float* b_f  = P_bf;
    const float* b_b  = P_bb;
    const float* femb = P_femb;
    __shared__ __align__(16) float As[2][BKK][BM + 4];
    __shared__ __align__(16) float Bs[2][BKK][BN];
    __shared__ int sw[BM], sr[BM], sf[BM];
    int bm = blockIdx.x * BM;
    int bn = blockIdx.y * BN;
    int tid = threadIdx.x;
    int am = tid >> 1, ak = (tid & 1) * 4;
    int bk = tid >> 5, bn4 = (tid & 31) * 4;
    int tx = tid & 15, ty = tid >> 4;

    for (int i = tid; i < BM; i += 256) {
        int m = bm + i;
        sw[i] = P_word[m];
        sr[i] = P_rec[m];
        sf[i] = P_feat[m];
    }
    __syncthreads();
    int myr = sr[am], myf = sf[am];
    const float* wrow = P_wemb + (size_t)sw[am]*WDD;

    ull acc2[8][4];
    #pragma unroll
    for (int i = 0; i < 8; i++)
        #pragma unroll
        for (int j = 0; j < 4; j++) acc2[i][j] = 0ull;

    float4 a4, b4;
    #define GATHER(t) {                                                          \
        int k = (t)*BKK + ak;                                                    \
        if (k + 3 < WDD) {                                                       \
            a4 = *(const float4*)(wrow + k);                                     \
        } else {                                                                 \
            float vv[4];                                                         \
            _Pragma("unroll")                                                    \
            for (int c = 0; c < 4; c++) {                                        \
                int kk2 = k + c;                                                 \
                float x = 0.f;                                                   \
                if (kk2 < WDD)           x = __ldg(wrow + kk2);                  \
                else if (kk2 < WDD+CHH)  x = g_charmax[myr*CHH + kk2 - WDD];     \
                else if (kk2 < INN)      x = __ldg(femb + myf*FDD + (kk2 - WDD - CHH)); \
                vv[c] = x;                                                       \
            }                                                                    \
            a4 = make_float4(vv[0], vv[1], vv[2], vv[3]);                        \
        }                                                                        \
        b4 = *(const float4*)(g_W + (size_t)((t)*BKK + bk)*N2P + bn + bn4);      \
    }
    #define STORE(buf) {                                                         \
        As[buf][ak+0][am] = a4.x; As[buf][ak+1][am] = a4.y;                      \
        As[buf][ak+2][am] = a4.z; As[buf][ak+3][am] = a4.w;                      \
        *(float4*)&Bs[buf][bk][bn4] = b4;                                        \
    }

    GATHER(0); STORE(0);
    __syncthreads();
    for (int t = 0; t < NT; t++) {
        int cur = t & 1;
        if (t + 1 < NT) GATHER(t + 1);
        #pragma unroll
        for (int kk = 0; kk < BKK; kk++) {
            float4 a0 = *(const float4*)&As[cur][kk][ty*8];
            float4 a1 = *(const float4*)&As[cur][kk][ty*8 + 4];
            ulonglong2 bL = *(const ulonglong2*)&Bs[cur][kk][tx*4];
            ulonglong2 bH = *(const ulonglong2*)&Bs[cur][kk][64 + tx*4];
            ull br2[4];
            br2[0] = bL.x; br2[1] = bL.y; br2[2] = bH.x; br2[3] = bH.y;
            float ar[8];
            ar[0]=a0.x; ar[1]=a0.y; ar[2]=a0.z; ar[3]=a0.w;
            ar[4]=a1.x; ar[5]=a1.y; ar[6]=a1.z; ar[7]=a1.w;
            #pragma unroll
            for (int i = 0; i < 8; i++) {
                ull a2 = fdup(ar[i]);
                #pragma unroll
                for (int j2 = 0; j2 < 4; j2++)
                    acc2[i][j2] = ffma2(a2, br2[j2], acc2[i][j2]);
            }
        }
        if (t + 1 < NT) STORE(cur ^ 1);
        __syncthreads();
    }

    #pragma unroll
    for (int i = 0; i < 8; i++) {
        int m = bm + ty*8 + i;
        #pragma unroll
        for (int j2 = 0; j2 < 4; j2++) {
            float2 v = fupk(acc2[i][j2]);
            int col = (j2 < 2) ? (tx*4 + 2*j2) : (64 + tx*4 + 2*(j2-2));
            int n0 = bn + col;
            if (n0 < N2) {
                float bias0 = (n0 < G4) ? __ldg(b_f + n0) : __ldg(b_b + n0 - G4);
                g_pre[(size_t)m*N2 + n0] = v.x + bias0;
            }
            int n1 = n0 + 1;
            if (n1 < N2) {
                float bias1 = (n1 < G4) ? __ldg(b_f + n1) : __ldg(b_b + n1 - G4);
                g_pre[(size_t)m*N2 + n1] = v.y + bias1;
            }
        }
    }
}

// ---------------- K3: LSTM recurrence — distributed activations ----------------
// thread (j,q): j = h-index (0..99), q = K-chunk AND gate slot (0..3)
// lane layout: lane = q*8 + (j%8)
// After butterfly reduce, lane q computes ONE activation:
//   q0: sig(i), q1: sig(f), q2: tanh(g), q3: sig(o)
// using the shared form act(x) = 1 - k/(e^{k*x}+1), k=1 (sig) or 2 (tanh),
// then shfl_xor 8/16/24 delivers all four to every lane (bit-identical values).
__global__ __launch_bounds__(416, 1)
void k_lstm() {
    int bx  = blockIdx.x;
    int dir = bx >> 6;
    int b   = bx & 63;
    const float* w = (dir == 0) ? P_whhf : P_whhb;
    int tid  = threadIdx.x;
    int lane = tid & 31;
    int q    = lane >> 3;
    int j    = (tid >> 5)*8 + (lane & 7);   // 0..103 (warp 12 partial)
    bool jok = (j < HH);
    float kf = (q == 2) ? 2.0f : 1.0f;      // tanh lane uses k=2

    __shared__ __align__(16) ull h_dup[2][104];   // 4 chunks x 26 (25 used + pad)

    ull wif[25], wgo[25];
    {
        int k0 = q*25;
        if (jok) {
            const float* wi = w + (size_t)j*HH        + k0;
            const float* wf = w + (size_t)(HH+j)*HH   + k0;
            const float* wg = w + (size_t)(2*HH+j)*HH + k0;
            const float* wo = w + (size_t)(3*HH+j)*HH + k0;
            #pragma unroll
            for (int t = 0; t < 25; t++) {
                wif[t] = fpk(__ldg(wi + t), __ldg(wf + t));
                wgo[t] = fpk(__ldg(wg + t), __ldg(wo + t));
            }
        } else {
            #pragma unroll
            for (int t = 0; t < 25; t++) { wif[t] = 0ull; wgo[t] = 0ull; }
        }
    }
    if (tid < 104) { h_dup[0][tid] = 0ull; h_dup[1][tid] = 0ull; }
    float c = 0.f, h = 0.f;
    int len = P_len[b];
    int hidx = (j/25)*26 + (j%25);   // h[j]'s slot in the padded layout
    __syncthreads();

    const float* preb = g_pre + (size_t)(b*SS)*N2 + dir*G4 + q*HH + j;
    int s0 = dir ? (SS-1) : 0;
    int ds = dir ? -1 : 1;

    #define CLAMPS(x) ((x) < 0 ? 0 : ((x) > SS-1 ? SS-1 : (x)))
    float p0 = jok ? __ldg(preb + (size_t)CLAMPS(s0)*N2)        : 0.f;
    float p1 = jok ? __ldg(preb + (size_t)CLAMPS(s0+ds)*N2)     : 0.f;
    float p2 = jok ? __ldg(preb + (size_t)CLAMPS(s0+2*ds)*N2)   : 0.f;

    int s = s0;
    for (int it = 0; it < SS; it++, s += ds) {
        int s3 = CLAMPS(s + 3*ds);
        float pnew = jok ? __ldg(preb + (size_t)s3*N2) : 0.f;

        int cur = it & 1;
        ull aif = (q == 0) ? fpk(p0, 0.f) : (q == 1) ? fpk(0.f, p0) : 0ull;
        ull ago = (q == 2) ? fpk(p0, 0.f) : (q == 3) ? fpk(0.f, p0) : 0ull;
        const ulonglong2* hd2 = (const ulonglong2*)&h_dup[cur][q*26];
        #pragma unroll
        for (int t = 0; t < 12; t++) {
            ulonglong2 hp = hd2[t];
            aif = ffma2(wif[2*t],   hp.x, aif);
            ago = ffma2(wgo[2*t],   hp.x, ago);
            aif = ffma2(wif[2*t+1], hp.y, aif);
            ago = ffma2(wgo[2*t+1], hp.y, ago);
        }
        {
            ull hp = h_dup[cur][q*26 + 24];
            aif = ffma2(wif[24], hp, aif);
            ago = ffma2(wgo[24], hp, ago);
        }
        aif = faddx2(aif, __shfl_xor_sync(0xffffffffu, aif, 8));
        ago = faddx2(ago, __shfl_xor_sync(0xffffffffu, ago, 8));
        aif = faddx2(aif, __shfl_xor_sync(0xffffffffu, aif, 16));
        ago = faddx2(ago, __shfl_xor_sync(0xffffffffu, ago, 16));
        float2 sif = fupk(aif);
        float2 sgo = fupk(ago);

        // this lane's gate input
        float inp = (q == 0) ? sif.x : (q == 1) ? sif.y : (q == 2) ? sgo.x : sgo.y;
        float e   = __expf(kf * inp);
        float act = 1.0f - __fdividef(kf, e + 1.0f);
        // exchange: a8/a16/a24 are the other three lanes' activations
        float a8  = __shfl_xor_sync(0xffffffffu, act, 8);
        float a16 = __shfl_xor_sync(0xffffffffu, act, 16);
        float a24 = __shfl_xor_sync(0xffffffffu, act, 24);
        // from q0's view: act=sig(i), a8=sig(f), a16=tanh(g), a24=sig(o)
        float cn = a8*c + act*a16;
        float e2 = __expf(2.0f * cn);
        float tc = 1.0f - __fdividef(2.0f, e2 + 1.0f);
        float hn = a24 * tc;
        if (s < len) { c = cn; h = hn; }   // meaningful only on q0 lanes
        if (q == 0 && jok) {
            h_dup[cur ^ 1][hidx] = fdup(h);
            g_lstm[(size_t)(b*SS + s)*(2*HH) + dir*HH + j] = h;
        }
        __syncthreads();
        p0 = p1; p1 = p2; p2 = pnew;
    }
    #undef CLAMPS
}

// ---------------- K4: emission projection (4 accumulator chains) ----------------
__global__ void k_feats() {
    const float* proj_w = P_pw;
    const float* proj_b = P_pb;
    __shared__ float rows[8][2*HH];
    int wrp = threadIdx.x >> 5;
    int lane = threadIdx.x & 31;
    int n = blockIdx.x*8 + wrp;
    const float* src = g_lstm + (size_t)n*(2*HH);
    for (int k = lane; k < 2*HH; k += 32)
        rows[wrp][k] = src[k];
    __syncwarp();
    if (lane < TT) {
        float a0 = 0.f, a1 = 0.f, a2 = 0.f, a3 = 0.f;
        #pragma unroll 4
        for (int k = 0; k < 2*HH; k += 4) {
            a0 += rows[wrp][k+0] * __ldg(proj_w + (k+0)*TT + lane);
            a1 += rows[wrp][k+1] * __ldg(proj_w + (k+1)*TT + lane);
            a2 += rows[wrp][k+2] * __ldg(proj_w + (k+2)*TT + lane);
            a3 += rows[wrp][k+3] * __ldg(proj_w + (k+3)*TT + lane);
        }
        g_feats[(size_t)n*TT + lane] = __ldg(proj_b + lane) + ((a0 + a1) + (a2 + a3));
    }
}

// ---------------- K5: Viterbi decode + backtrace (single-warp blocks) ----------------
__global__ void k_viterbi(float* __restrict__ out) {
    const float* trans = P_tr;
    const int*   lens  = P_len;
    int b = blockIdx.x;
    int j = threadIdx.x;
    __shared__ float tr[TT*TT];
    __shared__ float delta[TT];
    __shared__ unsigned char bp[(SS-1)*TT];
    for (int i = j; i < TT*TT; i += 32) tr[i] = trans[i];
    int len = lens[b];
    const float* fb = g_feats + (size_t)b*SS*TT;
    __syncwarp();
    if (j < TT) delta[j] = tr[START_TAG*TT + j] + __ldg(fb + j);
    __syncwarp();

    float fcur = (j < TT) ? __ldg(fb + TT + j) : 0.f;
    for (int t = 1; t < SS; t++) {
        float fnext = 0.f;
        if (j < TT && t < SS-1) fnext = __ldg(fb + (size_t)(t+1)*TT + j);
        float nd = 0.f; int nb = 0;
        if (j < TT) {
            float best = delta[0] + tr[j];
            int bi = 0;
            #pragma unroll
            for (int i = 1; i < TT; i++) {
                float sc = delta[i] + tr[i*TT + j];
                if (sc > best) { best = sc; bi = i; }
            }
            if (t < len) { nd = best + fcur; nb = bi; }
            else         { nd = delta[j];    nb = j;  }
        }
        __syncwarp();
        if (j < TT) { delta[j] = nd; bp[(t-1)*TT + j] = (unsigned char)nb; }
        __syncwarp();
        fcur = fnext;
    }
    if (j == 0) {
        float best = delta[0] + tr[STOP_TAG];
        int bi = 0;
        for (int i = 1; i < TT; i++) {
            float sc = delta[i] + tr[i*TT + STOP_TAG];
            if (sc > best) { best = sc; bi = i; }
        }
        int tag = bi;
        out[b*SS + SS-1] = (float)tag;
        for (int s = SS-2; s >= 0; s--) {
            tag = bp[s*TT + tag];
            out[b*SS + s] = (float)tag;
        }
    }
}

// ---------------- launcher ----------------
extern "C" void kernel_launch(void* const* d_in, const int* in_sizes, int n_in,
                              void* d_out, int out_size) {
    FixedPtrs fp;
    fp.n16 = 0; fp.n50 = 0;
    int n142 = 0, n40k = 0, n400 = 0;
    for (int i = 0; i < n_in; i++) {
        int s = in_sizes[i];
        const void* p = d_in[i];
        if (s == 15000000)      fp.wemb = (const float*)p;
        else if (s == 256000)   fp.chr  = (const int*)p;
        else if (s == 64)       fp.len  = (const int*)p;
        else if (s == 30000)    fp.cemb = (const float*)p;
        else if (s == 45000)    fp.cw   = (const float*)p;
        else if (s == 4400)     fp.pw   = (const float*)p;
        else if (s == 22)       fp.pb   = (const float*)p;
        else if (s == 484)      fp.tr   = (const float*)p;
        else if (s == 142000) { if (n142++ == 0) fp.wihf = (const float*)p; else fp.wihb = (const float*)p; }
        else if (s == 40000)  { if (n40k++ == 0) fp.whhf = (const float*)p; else fp.whhb = (const float*)p; }
        else if (s == 400)    { if (n400++ == 0) fp.bf   = (const float*)p; else fp.bb   = (const float*)p; }
        else if (s == 50)     { if (fp.n50 < 2) fp.c50[fp.n50++] = (const float*)p; }
        else if (s == 16000)  { if (fp.n16 < 5) fp.c16[fp.n16++] = (const int*)p; }
    }

    k_init<<<731, 512>>>(fp);                // launch 0 (resolve + buildW + charproj)
    k_charmax<<<NS/4, 256>>>();              // launch 1
    dim3 gg((NS + BM - 1)/BM, (N2P + BN - 1)/BN);
    k_gemm<<<gg, 256>>>();                   // launch 2
    k_lstm<<<128, 416>>>();                  // launch 3  <- ncu target
    k_feats<<<NS/8, 256>>>();                // launch 4
    k_viterbi<<<BB, 32>>>((float*)d_out);    // launch 5
}

// round 13
// speedup vs baseline: 1.1152x; 1.1152x over previous
#include <cuda_runtime.h>
#include <math.h>

// ---------------- problem constants ----------------
#define BB   64
#define SS   250
#define CLL  16
#define CVV  100
#define CHH  50
#define FDD  5
#define WDD  300
#define CDD  300
#define HH   100
#define G4   400      // 4*H
#define INN  355      // WD + CH + FD
#define KP   360      // padded K for GEMM
#define N2   800      // both directions' gates
#define N2P  896      // padded N for GEMM loads
#define NS   (BB*SS)  // 16000
#define TT   22
#define START_TAG 20
#define STOP_TAG  21

typedef unsigned long long ull;

// ---------------- resolved input pointers ----------------
__device__ const int   *P_word, *P_feat, *P_len, *P_char, *P_rec;
__device__ const float *P_cemb, *P_wemb, *P_femb, *P_cw, *P_cb;
__device__ const float *P_wihf, *P_whhf, *P_bf, *P_wihb, *P_whhb, *P_bb;
__device__ const float *P_pw, *P_pb, *P_tr;

// ---------------- scratch ----------------
__device__ float g_proj[CVV*3*CHH];
__device__ float g_charmax[NS*CHH];
__device__ float g_W[KP*N2P];
__device__ float g_pre[NS*N2];
__device__ float g_lstm[NS*(2*HH)];
__device__ float g_feats[NS*TT];

// MUFU-based activations (R11 formulas; rel_err 0.0)
__device__ __forceinline__ float sigf(float x) {
    return __fdividef(1.0f, 1.0f + __expf(-x));
}
__device__ __forceinline__ float tanhf_fast(float x) {
    float e = __expf(2.0f * x);
    return 1.0f - __fdividef(2.0f, e + 1.0f);
}

// ---------------- packed fp32x2 helpers ----------------
__device__ __forceinline__ ull ffma2(ull a, ull b, ull c) {
    ull d;
    asm("fma.rn.f32x2 %0, %1, %2, %3;" : "=l"(d) : "l"(a), "l"(b), "l"(c));
    return d;
}
__device__ __forceinline__ ull faddx2(ull a, ull b) {
    ull d;
    asm("add.rn.f32x2 %0, %1, %2;" : "=l"(d) : "l"(a), "l"(b));
    return d;
}
__device__ __forceinline__ ull fdup(float a) {
    ull r;
    asm("mov.b64 %0, {%1, %1};" : "=l"(r) : "f"(a));
    return r;
}
__device__ __forceinline__ ull fpk(float a, float b) {
    ull r;
    asm("mov.b64 %0, {%1, %2};" : "=l"(r) : "f"(a), "f"(b));
    return r;
}
__device__ __forceinline__ float2 fupk(ull v) {
    float2 f;
    asm("mov.b64 {%0, %1}, %2;" : "=f"(f.x), "=f"(f.y) : "l"(v));
    return f;
}

// ---------------- host-resolved fixed pointers ----------------
struct FixedPtrs {
    const float *wemb, *cemb, *cw, *pw, *pb, *tr;
    const float *wihf, *wihb, *whhf, *whhb, *bf, *bb;
    const int   *chr, *len;
    const int   *c16[5]; int n16;
    const float *c50[2]; int n50;
};

// ---------------- K0: fused resolve + coalesced buildW transpose + charproj ----------------
// block 0:          content classification
// blocks 1..336:    smem tile-transpose pack of w_ih into g_W (coalesced R+W)
// blocks 337..436:  char conv projection table
#define GT 28   // g2 tiles (28*32 = 896 = N2P)
#define KT 12   // k  tiles (12*32 = 384 >= KP)
__global__ __launch_bounds__(512, 2)
void k_init(FixedPtrs fp) {
    int bid = blockIdx.x;
    int tid = threadIdx.x;
    if (bid == 0) {
        int w = tid >> 5, lane = tid & 31;
        if (w < fp.n16 && w < 5) {
            const int* v = fp.c16[w];
            bool isrec = true, ble1 = true;
            int mn = 0x7fffffff, mx = -0x7fffffff;
            #pragma unroll
            for (int k = lane; k < 256; k += 32) {
                int x = v[k];
                if (x != k) isrec = false;
                unsigned u = (unsigned)x;
                if (((u)&0xFFu) > 1u || ((u>>8)&0xFFu) > 1u ||
                    ((u>>16)&0xFFu) > 1u || ((u>>24)&0xFFu) > 1u) ble1 = false;
                mn = min(mn, x); mx = max(mx, x);
            }
            isrec = __all_sync(0xffffffffu, isrec);
            ble1  = __all_sync(0xffffffffu, ble1);
            #pragma unroll
            for (int off = 16; off; off >>= 1) {
                mn = min(mn, __shfl_xor_sync(0xffffffffu, mn, off));
                mx = max(mx, __shfl_xor_sync(0xffffffffu, mx, off));
            }
            if (lane == 0) {
                if (isrec)                    P_rec  = v;
                else if (ble1)                { /* mask: unused */ }
                else if (mn >= 0 && mx <= 9)  P_feat = v;
                else if (mn >= 1 && mx <= 16) { /* charlen: unused */ }
                else                          P_word = v;
            }
        } else if (w == 5) {
            for (int j = 0; j < fp.n50; j++) {
                const float* f = fp.c50[j];
                bool nz = false;
                for (int k = lane; k < 50; k += 32) nz |= (f[k] != 0.0f);
                bool anynz = __any_sync(0xffffffffu, nz);
                if (lane == 0) { if (anynz) P_femb = f; else P_cb = f; }
            }
        } else if (w == 6 && lane == 0) {
            P_wemb = fp.wemb; P_cemb = fp.cemb; P_cw = fp.cw;
            P_pw = fp.pw; P_pb = fp.pb; P_tr = fp.tr;
            P_wihf = fp.wihf; P_wihb = fp.wihb;
            P_whhf = fp.whhf; P_whhb = fp.whhb;
            P_bf = fp.bf; P_bb = fp.bb;
            P_char = fp.chr; P_len = fp.len;
        }
    } else if (bid <= GT*KT) {
        // coalesced transpose: wih[g2][k] -> g_W[k][g2]
        __shared__ float tile[32][33];
        int t  = bid - 1;
        int kt = t / GT;          // k tile
        int gt = t % GT;          // g2 tile
        int tx  = tid & 31;
        int ty0 = tid >> 5;       // 0..15
        #pragma unroll
        for (int h2 = 0; h2 < 2; h2++) {
            int ty = ty0 + h2*16;
            int g2 = gt*32 + ty;
            int k  = kt*32 + tx;
            float v = 0.f;
            if (k < INN && g2 < N2)
                v = (g2 < G4) ? fp.wihf[g2*INN + k] : fp.wihb[(g2-G4)*INN + k];
            tile[ty][tx] = v;
        }
        __syncthreads();
        #pragma unroll
        for (int h2 = 0; h2 < 2; h2++) {
            int r  = ty0 + h2*16;        // k index within tile
            int k2 = kt*32 + r;
            int g2 = gt*32 + tx;
            if (k2 < KP)
                g_W[(size_t)k2*N2P + g2] = tile[tx][r];
        }
    } else {
        const float* char_emb = fp.cemb;
        const float* conv_w   = fp.cw;
        __shared__ float sce[CDD];
        int c = bid - (GT*KT + 1);
        for (int d = tid; d < CDD; d += blockDim.x)
            sce[d] = char_emb[c*CDD + d];
        __syncthreads();
        if (tid < 3*CHH) {
            int k = tid / CHH, o = tid % CHH;
            float acc = 0.f;
            #pragma unroll 4
            for (int d = 0; d < CDD; d++)
                acc += __ldg(conv_w + (o*CDD + d)*3 + k) * sce[d];
            g_proj[(c*3 + k)*CHH + o] = acc;
        }
    }
}

// ---------------- K1: char conv + max-pool ----------------
__global__ void k_charmax() {
    const int*   batch_char = P_char;
    const float* conv_b     = P_cb;
    __shared__ int chs[4][CLL];
    int t = threadIdx.x & 63;
    int ns = threadIdx.x >> 6;
    int n = blockIdx.x*4 + ns;
    if (t < CLL) chs[ns][t] = batch_char[n*CLL + t];
    __syncthreads();
    if (t < CHH) {
        float bo = conv_b[t];
        float best = -1e30f;
        #pragma unroll
        for (int p = 0; p < CLL; p++) {
            float v = bo;
            #pragma unroll
            for (int k = 0; k < 3; k++) {
                int q = p + k - 1;
                if (q >= 0 && q < CLL)
                    v += __ldg(&g_proj[(chs[ns][q]*3 + k)*CHH + t]);
            }
            best = fmaxf(best, v);
        }
        g_charmax[n*CHH + t] = best;
    }
}

// ---------------- K2: SGEMM, fused A-gather, double-buffered ----------------
#define BM 128
#define BN 128
#define BKK 8
#define NT (KP/BKK)   // 45
__global__ __launch_bounds__(256, 2)
void k_gemm() {
    const float* b_f  = P_bf;
    const float* b_b  = P_bb;
    const float* femb = P_femb;
    __shared__ __align__(16) float As[2][BKK][BM + 4];
    __shared__ __align__(16) float Bs[2][BKK][BN];
    __shared__ int sw[BM], sr[BM], sf[BM];
    int bm = blockIdx.x * BM;
    int bn = blockIdx.y * BN;
    int tid = threadIdx.x;
    int am = tid >> 1, ak = (tid & 1) * 4;
    int bk = tid >> 5, bn4 = (tid & 31) * 4;
    int tx = tid & 15, ty = tid >> 4;

    for (int i = tid; i < BM; i += 256) {
        int m = bm + i;
        sw[i] = P_word[m];
        sr[i] = P_rec[m];
        sf[i] = P_feat[m];
    }
    __syncthreads();
    int myr = sr[am], myf = sf[am];
    const float* wrow = P_wemb + (size_t)sw[am]*WDD;

    ull acc2[8][4];
    #pragma unroll
    for (int i = 0; i < 8; i++)
        #pragma unroll
        for (int j = 0; j < 4; j++) acc2[i][j] = 0ull;

    float4 a4, b4;
    #define GATHER(t) {                                                          \
        int k = (t)*BKK + ak;                                                    \
        if (k + 3 < WDD) {                                                       \
            a4 = *(const float4*)(wrow + k);                                     \
        } else {                                                                 \
            float vv[4];                                                         \
            _Pragma("unroll")                                                    \
            for (int c = 0; c < 4; c++) {                                        \
                int kk2 = k + c;                                                 \
                float x = 0.f;                                                   \
                if (kk2 < WDD)           x = __ldg(wrow + kk2);                  \
                else if (kk2 < WDD+CHH)  x = g_charmax[myr*CHH + kk2 - WDD];     \
                else if (kk2 < INN)      x = __ldg(femb + myf*FDD + (kk2 - WDD - CHH)); \
                vv[c] = x;                                                       \
            }                                                                    \
            a4 = make_float4(vv[0], vv[1], vv[2], vv[3]);                        \
        }                                                                        \
        b4 = *(const float4*)(g_W + (size_t)((t)*BKK + bk)*N2P + bn + bn4);      \
    }
    #define STORE(buf) {                                                         \
        As[buf][ak+0][am] = a4.x; As[buf][ak+1][am] = a4.y;                      \
        As[buf][ak+2][am] = a4.z; As[buf][ak+3][am] = a4.w;                      \
        *(float4*)&Bs[buf][bk][bn4] = b4;                                        \
    }

    GATHER(0); STORE(0);
    __syncthreads();
    for (int t = 0; t < NT; t++) {
        int cur = t & 1;
        if (t + 1 < NT) GATHER(t + 1);
        #pragma unroll
        for (int kk = 0; kk < BKK; kk++) {
            float4 a0 = *(const float4*)&As[cur][kk][ty*8];
            float4 a1 = *(const float4*)&As[cur][kk][ty*8 + 4];
            ulonglong2 bL = *(const ulonglong2*)&Bs[cur][kk][tx*4];
            ulonglong2 bH = *(const ulonglong2*)&Bs[cur][kk][64 + tx*4];
            ull br2[4];
            br2[0] = bL.x; br2[1] = bL.y; br2[2] = bH.x; br2[3] = bH.y;
            float ar[8];
            ar[0]=a0.x; ar[1]=a0.y; ar[2]=a0.z; ar[3]=a0.w;
            ar[4]=a1.x; ar[5]=a1.y; ar[6]=a1.z; ar[7]=a1.w;
            #pragma unroll
            for (int i = 0; i < 8; i++) {
                ull a2 = fdup(ar[i]);
                #pragma unroll
                for (int j2 = 0; j2 < 4; j2++)
                    acc2[i][j2] = ffma2(a2, br2[j2], acc2[i][j2]);
            }
        }
        if (t + 1 < NT) STORE(cur ^ 1);
        __syncthreads();
    }

    #pragma unroll
    for (int i = 0; i < 8; i++) {
        int m = bm + ty*8 + i;
        #pragma unroll
        for (int j2 = 0; j2 < 4; j2++) {
            float2 v = fupk(acc2[i][j2]);
            int col = (j2 < 2) ? (tx*4 + 2*j2) : (64 + tx*4 + 2*(j2-2));
            int n0 = bn + col;
            if (n0 < N2) {
                float bias0 = (n0 < G4) ? __ldg(b_f + n0) : __ldg(b_b + n0 - G4);
                g_pre[(size_t)m*N2 + n0] = v.x + bias0;
            }
            int n1 = n0 + 1;
            if (n1 < N2) {
                float bias1 = (n1 < G4) ? __ldg(b_f + n1) : __ldg(b_b + n1 - G4);
                g_pre[(size_t)m*N2 + n1] = v.y + bias1;
            }
        }
    }
}

// ---------------- K3: LSTM recurrence — R11 version (best known: 169us) ----------------
__global__ __launch_bounds__(416, 1)
void k_lstm() {
    int bx  = blockIdx.x;
    int dir = bx >> 6;
    int b   = bx & 63;
    const float* w = (dir == 0) ? P_whhf : P_whhb;
    int tid  = threadIdx.x;
    int lane = tid & 31;
    int q    = lane >> 3;
    int j    = (tid >> 5)*8 + (lane & 7);   // 0..103 (warp 12 partial)
    bool jok = (j < HH);

    __shared__ __align__(16) ull h_dup[2][104];   // 4 chunks x 26 (25 used + pad)

    ull wif[25], wgo[25];
    {
        int k0 = q*25;
        if (jok) {
            const float* wi = w + (size_t)j*HH        + k0;
            const float* wf = w + (size_t)(HH+j)*HH   + k0;
            const float* wg = w + (size_t)(2*HH+j)*HH + k0;
            const float* wo = w + (size_t)(3*HH+j)*HH + k0;
            #pragma unroll
            for (int t = 0; t < 25; t++) {
                wif[t] = fpk(__ldg(wi + t), __ldg(wf + t));
                wgo[t] = fpk(__ldg(wg + t), __ldg(wo + t));
            }
        } else {
            #pragma unroll
            for (int t = 0; t < 25; t++) { wif[t] = 0ull; wgo[t] = 0ull; }
        }
    }
    if (tid < 104) { h_dup[0][tid] = 0ull; h_dup[1][tid] = 0ull; }
    float c = 0.f, h = 0.f;
    int len = P_len[b];
    int hidx = (j/25)*26 + (j%25);   // h[j]'s slot in the padded layout
    __syncthreads();

    const float* preb = g_pre + (size_t)(b*SS)*N2 + dir*G4 + q*HH + j;
    int s0 = dir ? (SS-1) : 0;
    int ds = dir ? -1 : 1;

    #define CLAMPS(x) ((x) < 0 ? 0 : ((x) > SS-1 ? SS-1 : (x)))
    float p0 = jok ? __ldg(preb + (size_t)CLAMPS(s0)*N2)        : 0.f;
    float p1 = jok ? __ldg(preb + (size_t)CLAMPS(s0+ds)*N2)     : 0.f;
    float p2 = jok ? __ldg(preb + (size_t)CLAMPS(s0+2*ds)*N2)   : 0.f;

    int s = s0;
    for (int it = 0; it < SS; it++, s += ds) {
        int s3 = CLAMPS(s + 3*ds);
        float pnew = jok ? __ldg(preb + (size_t)s3*N2) : 0.f;

        int cur = it & 1;
        ull aif = (q == 0) ? fpk(p0, 0.f) : (q == 1) ? fpk(0.f, p0) : 0ull;
        ull ago = (q == 2) ? fpk(p0, 0.f) : (q == 3) ? fpk(0.f, p0) : 0ull;
        const ulonglong2* hd2 = (const ulonglong2*)&h_dup[cur][q*26];
        #pragma unroll
        for (int t = 0; t < 12; t++) {
            ulonglong2 hp = hd2[t];
            aif = ffma2(wif[2*t],   hp.x, aif);
            ago = ffma2(wgo[2*t],   hp.x, ago);
            aif = ffma2(wif[2*t+1], hp.y, aif);
            ago = ffma2(wgo[2*t+1], hp.y, ago);
        }
        {
            ull hp = h_dup[cur][q*26 + 24];
            aif = ffma2(wif[24], hp, aif);
            ago = ffma2(wgo[24], hp, ago);
        }
        aif = faddx2(aif, __shfl_xor_sync(0xffffffffu, aif, 8));
        ago = faddx2(ago, __shfl_xor_sync(0xffffffffu, ago, 8));
        aif = faddx2(aif, __shfl_xor_sync(0xffffffffu, aif, 16));
        ago = faddx2(ago, __shfl_xor_sync(0xffffffffu, ago, 16));
        float2 sif = fupk(aif);
        float2 sgo = fupk(ago);
        float cn = sigf(sif.y)*c + sigf(sif.x)*tanhf_fast(sgo.x);
        float hn = sigf(sgo.y)*tanhf_fast(cn);
        if (s < len) { c = cn; h = hn; }
        if (q == 0 && jok) {
            h_dup[cur ^ 1][hidx] = fdup(h);
            g_lstm[(size_t)(b*SS + s)*(2*HH) + dir*HH + j] = h;
        }
        __syncthreads();
        p0 = p1; p1 = p2; p2 = pnew;
    }
    #undef CLAMPS
}

// ---------------- K4: emission projection (4 accumulator chains) ----------------
__global__ void k_feats() {
    const float* proj_w = P_pw;
    const float* proj_b = P_pb;
    __shared__ float rows[8][2*HH];
    int wrp = threadIdx.x >> 5;
    int lane = threadIdx.x & 31;
    int n = blockIdx.x*8 + wrp;
    const float* src = g_lstm + (size_t)n*(2*HH);
    for (int k = lane; k < 2*HH; k += 32)
        rows[wrp][k] = src[k];
    __syncwarp();
    if (lane < TT) {
        float a0 = 0.f, a1 = 0.f, a2 = 0.f, a3 = 0.f;
        #pragma unroll 4
        for (int k = 0; k < 2*HH; k += 4) {
            a0 += rows[wrp][k+0] * __ldg(proj_w + (k+0)*TT + lane);
            a1 += rows[wrp][k+1] * __ldg(proj_w + (k+1)*TT + lane);
            a2 += rows[wrp][k+2] * __ldg(proj_w + (k+2)*TT + lane);
            a3 += rows[wrp][k+3] * __ldg(proj_w + (k+3)*TT + lane);
        }
        g_feats[(size_t)n*TT + lane] = __ldg(proj_b + lane) + ((a0 + a1) + (a2 + a3));
    }
}

// ---------------- K5: Viterbi — tree argmax (depth 5 vs 21 serial) ----------------
// tree keeps first-max semantics: strict '>' replacement, left slot always
// holds the smaller original index.
__device__ __forceinline__ void argmax22(const float* sc, float& bv, int& bi) {
    float v[22]; int ix[22];
    #pragma unroll
    for (int i = 0; i < 22; i++) { v[i] = sc[i]; ix[i] = i; }
    #pragma unroll
    for (int st = 16; st >= 1; st >>= 1) {
        #pragma unroll
        for (int i = 0; i < 22; i++) {
            if (i < st && i + st < 22) {
                bool r = v[i + st] > v[i];
                v[i]  = r ? v[i + st]  : v[i];
                ix[i] = r ? ix[i + st] : ix[i];
            }
        }
    }
    bv = v[0]; bi = ix[0];
}

__global__ void k_viterbi(float* __restrict__ out) {
    const float* trans = P_tr;
    const int*   lens  = P_len;
    int b = blockIdx.x;
    int j = threadIdx.x;
    __shared__ float tr[TT*TT];
    __shared__ float delta[TT];
    __shared__ unsigned char bp[(SS-1)*TT];
    for (int i = j; i < TT*TT; i += 32) tr[i] = trans[i];
    int len = lens[b];
    const float* fb = g_feats + (size_t)b*SS*TT;
    __syncwarp();
    if (j < TT) delta[j] = tr[START_TAG*TT + j] + __ldg(fb + j);
    __syncwarp();

    float fcur = (j < TT) ? __ldg(fb + TT + j) : 0.f;
    for (int t = 1; t < SS; t++) {
        float fnext = 0.f;
        if (j < TT && t < SS-1) fnext = __ldg(fb + (size_t)(t+1)*TT + j);
        float nd = 0.f; int nb = 0;
        if (j < TT) {
            float sc[TT];
            #pragma unroll
            for (int i = 0; i < TT; i++) sc[i] = delta[i] + tr[i*TT + j];
            float best; int bi;
            argmax22(sc, best, bi);
            if (t < len) { nd = best + fcur; nb = bi; }
            else         { nd = delta[j];    nb = j;  }
        }
        __syncwarp();
        if (j < TT) { delta[j] = nd; bp[(t-1)*TT + j] = (unsigned char)nb; }
        __syncwarp();
        fcur = fnext;
    }
    if (j == 0) {
        float sc[TT];
        #pragma unroll
        for (int i = 0; i < TT; i++) sc[i] = delta[i] + tr[i*TT + STOP_TAG];
        float best; int bi;
        argmax22(sc, best, bi);
        int tag = bi;
        out[b*SS + SS-1] = (float)tag;
        for (int s = SS-2; s >= 0; s--) {
            tag = bp[s*TT + tag];
            out[b*SS + s] = (float)tag;
        }
    }
}

// ---------------- launcher ----------------
extern "C" void kernel_launch(void* const* d_in, const int* in_sizes, int n_in,
                              void* d_out, int out_size) {
    FixedPtrs fp;
    fp.n16 = 0; fp.n50 = 0;
    int n142 = 0, n40k = 0, n400 = 0;
    for (int i = 0; i < n_in; i++) {
        int s = in_sizes[i];
        const void* p = d_in[i];
        if (s == 15000000)      fp.wemb = (const float*)p;
        else if (s == 256000)   fp.chr  = (const int*)p;
        else if (s == 64)       fp.len  = (const int*)p;
        else if (s == 30000)    fp.cemb = (const float*)p;
        else if (s == 45000)    fp.cw   = (const float*)p;
        else if (s == 4400)     fp.pw   = (const float*)p;
        else if (s == 22)       fp.pb   = (const float*)p;
        else if (s == 484)      fp.tr   = (const float*)p;
        else if (s == 142000) { if (n142++ == 0) fp.wihf = (const float*)p; else fp.wihb = (const float*)p; }
        else if (s == 40000)  { if (n40k++ == 0) fp.whhf = (const float*)p; else fp.whhb = (const float*)p; }
        else if (s == 400)    { if (n400++ == 0) fp.bf   = (const float*)p; else fp.bb   = (const float*)p; }
        else if (s == 50)     { if (fp.n50 < 2) fp.c50[fp.n50++] = (const float*)p; }
        else if (s == 16000)  { if (fp.n16 < 5) fp.c16[fp.n16++] = (const int*)p; }
    }

    k_init<<<1 + GT*KT + CVV, 512>>>(fp);    // launch 0 (resolve + transposeW + charproj)
    k_charmax<<<NS/4, 256>>>();              // launch 1
    dim3 gg((NS + BM - 1)/BM, (N2P + BN - 1)/BN);
    k_gemm<<<gg, 256>>>();                   // launch 2
    k_lstm<<<128, 416>>>();                  // launch 3  <- ncu target (control: expect ~169us)
    k_feats<<<NS/8, 256>>>();                // launch 4
    k_viterbi<<<BB, 32>>>((float*)d_out);    // launch 5
}